// round 16
// baseline (speedup 1.0000x reference)
#include <cuda_runtime.h>
#include <stdint.h>

// Problem constants
#define HWp   65536      // 256*256
#define Bp    2
#define Jp    512
#define JJp   (Jp*Jp)    // 262144
#define CAPp  16384      // candidate capacity per batch (expected ~7.3k)
#define THp   0.008f
#define J2Lp  10.0f
#define SCALEp 5.0f
#define NBINS 4096       // histogram bins (12 bits per level)
#define SELC  1024       // compaction capacity (S ~= 515 after 2-level select)
#define RADp  3.16227766f // sqrt(10): max distance that can ever match
#define ZERO4 ((Bp*JJp*9)/4)  // float4 count of the ENTIRE output region = 1179648
#define TILES 64              // 32x32-pixel NMS tiles per batch (8x8)
#define ZBLKC 128             // zero chunks per batch in k_cand (2048 float4 each)
#define ZC4   (Bp*ZBLKC*2048) // float4s zeroed by k_cand = 524288
#define ZBLKT 320             // zero chunks in k_topk (2048 float4 each) = 655360

// Scratch (static device globals — no allocation allowed)
__device__ unsigned long long  g_ckey[Bp][CAPp];
__device__ int                 g_ccnt[Bp];        // zero-init; reset by k_match
__device__ int                 g_nvalid[Bp];
__device__ float2              g_juncs[Bp][Jp];
__device__ int                 g_cellStart[Bp][1025];  // CSR over 32x32 cells of 8px
__device__ float4              g_gpack[Bp][Jp];        // (x, y, idx_bits, 0) cell order

__device__ __forceinline__ float sigf(float x) { return 1.0f / (1.0f + expf(-x)); }

// ---------------------------------------------------------------------------
// K1: fused softmax-prob + 3x3 NMS + candidate append. 32x32-pixel tiles with
// a 34x34 halo in smem; 1024-thread blocks; warp-aggregated candidate append.
// Extra blocks zero 8.4 MB of the output in SMALL 32KB chunks — the zeroing
// store stream, not the expf tiles, is this kernel's critical path, so fine
// chunks balance it across all SMs/SMSPs.
// prob = softmax(raw[:,5:7],axis=1)[:,1] with ONE expf (one of the two
// exponentials is exactly 1.0f after max-subtraction) -> bit-identical.
// key = (~float_bits(score) << 32) | pixel -> ascending == score desc,
// pixel-index asc on ties (matches jax.lax.top_k ordering).
// ---------------------------------------------------------------------------
__global__ void __launch_bounds__(1024) k_cand_zero(const float* __restrict__ raw,
                                                    float4* __restrict__ zdst) {
    int b = blockIdx.y;
    if (blockIdx.x >= TILES) {                     // zeroing chunks: [0, ZC4)
        int zi = ((blockIdx.x - TILES) + b * ZBLKC) * 2048 + threadIdx.x;
        float4 z = make_float4(0.f, 0.f, 0.f, 0.f);
        zdst[zi] = z;
        zdst[zi + 1024] = z;
        return;
    }
    __shared__ float sp[34 * 34];                  // 32x32 tile + 1px halo
    int tile = blockIdx.x;
    int tx0 = (tile & 7) << 5;
    int ty0 = (tile >> 3) << 5;
    const float* r5p = raw + (size_t)b * 9 * HWp + 5 * HWp;
    const float* r6p = raw + (size_t)b * 9 * HWp + 6 * HWp;

    // halo fill: 1156 entries, 2 iterations of 1024 threads
    #pragma unroll
    for (int it = 0; it < 2; it++) {
        int i = threadIdx.x + it * 1024;
        if (i < 34 * 34) {
            int hx = tx0 - 1 + (i % 34);
            int hy = ty0 - 1 + (i / 34);
            float v = -1.0f;                       // OOB: below any prob (>0)
            if ((unsigned)hx < 256u && (unsigned)hy < 256u) {
                int p = (hy << 8) + hx;
                float r5 = r5p[p];
                float r6 = r6p[p];
                float e  = expf(-fabsf(r6 - r5));
                v = (r6 >= r5) ? 1.0f / (e + 1.0f) : e / (1.0f + e);
            }
            sp[i] = v;
        }
    }
    __syncthreads();

    // NMS: one pixel per thread; no early return (ballot needs full warp)
    int lane = threadIdx.x & 31;
    int lx = threadIdx.x & 31;
    int ly = threadIdx.x >> 5;
    int c = (ly + 1) * 34 + (lx + 1);
    float a = sp[c];
    bool keep = false;
    if (a > THp) {
        float mx;
        mx = fmaxf(sp[c - 35], sp[c - 34]);
        mx = fmaxf(mx, sp[c - 33]);
        mx = fmaxf(mx, sp[c - 1]);
        mx = fmaxf(mx, sp[c + 1]);
        mx = fmaxf(mx, sp[c + 33]);
        mx = fmaxf(mx, sp[c + 34]);
        mx = fmaxf(mx, sp[c + 35]);
        keep = (a >= mx);                          // a == maxpool(a) semantics
    }
    unsigned mask = __ballot_sync(0xffffffffu, keep);
    if (keep) {
        int leader = __ffs(mask) - 1;
        int rank = __popc(mask & ((1u << lane) - 1u));
        int base;
        if (lane == leader) base = atomicAdd(&g_ccnt[b], __popc(mask));
        base = __shfl_sync(mask, base, leader);
        int pos = base + rank;
        if (pos < CAPp) {
            int p = ((ty0 + ly) << 8) + (tx0 + lx);
            unsigned inv = ~__float_as_uint(a);
            g_ckey[b][pos] = (((unsigned long long)inv) << 32) | (unsigned)p;
        }
    }
}

// ---------------------------------------------------------------------------
// K2: two-level radix select, barrier-lean bitonic sort (warp-shuffle
// sub-stages), junction decode, CSR spatial grid build. Blocks 0..Bp-1 do the
// real work; blocks >= Bp zero the remaining 10.5 MB in 32KB chunks on the
// otherwise-idle SMs (done before k_match by stream order).
// ---------------------------------------------------------------------------
struct SmemT {
    union {
        int hist[NBINS];                 // histogram (both levels) / scan
        int cnt1[1024];                  // cell counts, then fill cursors
    } u;
    unsigned long long sel[SELC];
    int warpsum[32];
    int sT, sCum, sSel;
};

// Find smallest bin T with cumulative >= target over sm.u.hist (4 bins/thread).
// Writes sm.sT (bin) and sm.sCum (inclusive cumulative through T).
// Caller must __syncthreads() before reading sm.sT / sm.sCum.
__device__ __forceinline__ void scan_find_bin(SmemT& sm, int target,
                                              int tid, int lane, int wid) {
    int base = tid * 4;
    int h0 = sm.u.hist[base], h1 = sm.u.hist[base+1];
    int h2 = sm.u.hist[base+2], h3 = sm.u.hist[base+3];
    int tot = h0 + h1 + h2 + h3;
    int inc = tot;
    #pragma unroll
    for (int d = 1; d < 32; d <<= 1) {
        int n = __shfl_up_sync(0xffffffffu, inc, d);
        if (lane >= d) inc += n;
    }
    if (lane == 31) sm.warpsum[wid] = inc;
    __syncthreads();
    if (wid == 0) {
        int v = sm.warpsum[lane];
        int i2 = v;
        #pragma unroll
        for (int d = 1; d < 32; d <<= 1) {
            int n = __shfl_up_sync(0xffffffffu, i2, d);
            if (lane >= d) i2 += n;
        }
        sm.warpsum[lane] = i2 - v;   // exclusive warp offsets
    }
    __syncthreads();
    int run = sm.warpsum[wid] + inc - tot;   // exclusive prefix for this thread
    int hh[4] = {h0, h1, h2, h3};
    #pragma unroll
    for (int i = 0; i < 4; i++) {
        run += hh[i];
        if (run >= target && run - hh[i] < target) { sm.sT = base + i; sm.sCum = run; }
    }
}

__device__ __forceinline__ unsigned long long bx(unsigned long long v, int j) {
    return __shfl_xor_sync(0xffffffffu, v, j);
}

__global__ void __launch_bounds__(1024) k_topk(const float* __restrict__ raw,
                                               float4* __restrict__ zdst) {
    __shared__ SmemT sm;
    if (blockIdx.x >= Bp) {                        // zeroing chunks: [ZC4, ZERO4)
        int base = ZC4 + (blockIdx.x - Bp) * 2048 + threadIdx.x;
        float4 z = make_float4(0.f, 0.f, 0.f, 0.f);
        zdst[base] = z;
        zdst[base + 1024] = z;
        return;
    }
    int b = blockIdx.x;
    int tid = threadIdx.x;
    int lane = tid & 31, wid = tid >> 5;
    int cnt = min(g_ccnt[b], CAPp);
    int target = min(Jp, cnt);

    if (cnt == 0) {   // defensive; never hit with this data
        if (tid < Jp) g_juncs[b][tid] = make_float2(0.f, 0.f);
        g_cellStart[b][tid] = 0;
        if (tid == 0) { g_cellStart[b][1024] = 0; g_nvalid[b] = 0; }
        return;
    }

    // --- level 1: histogram over key bits [52:64) ---
    for (int i = tid; i < NBINS; i += 1024) sm.u.hist[i] = 0;
    __syncthreads();
    for (int i = tid; i < cnt; i += 1024)
        atomicAdd(&sm.u.hist[(int)(g_ckey[b][i] >> 52)], 1);
    __syncthreads();
    scan_find_bin(sm, target, tid, lane, wid);
    __syncthreads();
    int T1 = sm.sT;
    int cntBefore = sm.sCum - sm.u.hist[T1];   // keys strictly below bin T1
    __syncthreads();                           // all reads done before reuse

    // --- level 2: histogram of bin-T1 keys over bits [40:52) ---
    for (int i = tid; i < NBINS; i += 1024) sm.u.hist[i] = 0;
    if (tid == 0) sm.sSel = 0;
    __syncthreads();
    for (int i = tid; i < cnt; i += 1024) {
        unsigned long long key = g_ckey[b][i];
        if ((int)(key >> 52) == T1)
            atomicAdd(&sm.u.hist[(int)(key >> 40) & 0xFFF], 1);
    }
    __syncthreads();
    scan_find_bin(sm, target - cntBefore, tid, lane, wid);
    __syncthreads();
    int T2 = sm.sT;
    int S = min(cntBefore + sm.sCum, SELC);    // S ~= target + few collisions

    // --- compact the selected superset ---
    for (int i = tid; i < cnt; i += 1024) {
        unsigned long long key = g_ckey[b][i];
        int b1 = (int)(key >> 52);
        if (b1 < T1 || (b1 == T1 && ((int)(key >> 40) & 0xFFF) <= T2)) {
            int pos = atomicAdd(&sm.sSel, 1);
            if (pos < SELC) sm.sel[pos] = key;
        }
    }
    __syncthreads();
    if (tid >= S) sm.sel[tid] = ~0ULL;        // pad to M=1024
    __syncthreads();

    // --- bitonic sort of M=1024, barrier-lean:
    //     stages k=2..32 fully in registers (intra-warp shuffles);
    //     stages k>=64: smem passes for j>=32, 5-shuffle register tail.
    //     Same comparison network as a plain bitonic sort -> identical order.
    {
        unsigned long long e = sm.sel[tid];
        #pragma unroll
        for (int k = 2; k <= 32; k <<= 1) {
            #pragma unroll
            for (int j = k >> 1; j > 0; j >>= 1) {
                unsigned long long o = bx(e, j);
                bool takeMin = ((tid & k) == 0) == ((tid & j) == 0);
                e = ((e < o) == takeMin) ? e : o;
            }
        }
        sm.sel[tid] = e;
        __syncthreads();
        for (int k = 64; k <= 1024; k <<= 1) {
            for (int j = k >> 1; j >= 32; j >>= 1) {
                int ixj = tid ^ j;
                if (ixj > tid) {
                    unsigned long long a = sm.sel[tid], c2 = sm.sel[ixj];
                    bool up = ((tid & k) == 0);
                    if ((a > c2) == up) { sm.sel[tid] = c2; sm.sel[ixj] = a; }
                }
                __syncthreads();
            }
            e = sm.sel[tid];
            #pragma unroll
            for (int j = 16; j > 0; j >>= 1) {
                unsigned long long o = bx(e, j);
                bool takeMin = ((tid & k) == 0) == ((tid & j) == 0);
                e = ((e < o) == takeMin) ? e : o;
            }
            sm.sel[tid] = e;
            __syncthreads();
        }
    }

    int nv = target;
    if (tid == 0) g_nvalid[b] = nv;

    // --- decode junction tid (one thread per junction) ---
    float qx = 0.f, qy = 0.f;
    int myCell = -1;
    const float* rb = raw + (size_t)b * 9 * HWp;
    if (tid < Jp) {
        if (tid < nv) {
            unsigned long long key = sm.sel[tid];
            int p = (int)(key & 0xFFFFFFFFu);
            float offx = sigf(rb[7 * HWp + p]) - 0.5f;
            float offy = sigf(rb[8 * HWp + p]) - 0.5f;
            qx = (float)(p & 255) + offx + 0.5f;
            qy = (float)(p >> 8) + offy + 0.5f;
            myCell = (((int)qy >> 3) << 5) + ((int)qx >> 3);   // 32x32 cells of 8px
        }
        g_juncs[b][tid] = make_float2(qx, qy);
    }
    __syncthreads();          // done with sel/hist before reuse

    // --- build CSR cell grid ---
    sm.u.cnt1[tid] = 0;
    __syncthreads();
    if (myCell >= 0) atomicAdd(&sm.u.cnt1[myCell], 1);
    __syncthreads();
    int v = sm.u.cnt1[tid];
    int inc2 = v;
    #pragma unroll
    for (int d = 1; d < 32; d <<= 1) {
        int n = __shfl_up_sync(0xffffffffu, inc2, d);
        if (lane >= d) inc2 += n;
    }
    if (lane == 31) sm.warpsum[wid] = inc2;
    __syncthreads();
    if (wid == 0) {
        int vv = sm.warpsum[lane];
        int i2 = vv;
        #pragma unroll
        for (int d = 1; d < 32; d <<= 1) {
            int n = __shfl_up_sync(0xffffffffu, i2, d);
            if (lane >= d) i2 += n;
        }
        sm.warpsum[lane] = i2 - vv;
    }
    __syncthreads();
    int excl = sm.warpsum[wid] + inc2 - v;
    g_cellStart[b][tid] = excl;
    if (tid == 1023) g_cellStart[b][1024] = excl + v;   // == nv
    __syncthreads();
    sm.u.cnt1[tid] = excl;     // fill cursors
    __syncthreads();
    if (myCell >= 0) {
        int pos = atomicAdd(&sm.u.cnt1[myCell], 1);
        g_gpack[b][pos] = make_float4(qx, qy, __int_as_float(tid), 0.f);
    }
}

// ---------------------------------------------------------------------------
// Pruned nearest-junction search with row-contiguous CSR scan; packed float4
// (x, y, idx_bits) = one LDG.128 per junction. (d, idx) lexicographic min
// reproduces the reference argmin first-index tie-break exactly.
// ---------------------------------------------------------------------------
__device__ __forceinline__ void nearest(const float4* __restrict__ gp,
                                        const int* __restrict__ cs,
                                        float ex, float ey,
                                        float& bd, int& bi) {
    int cx0 = ((int)fmaxf(ex - RADp, 0.0f)) >> 3;
    int cx1 = ((int)fminf(ex + RADp, 255.0f)) >> 3;
    int cy0 = ((int)fmaxf(ey - RADp, 0.0f)) >> 3;
    int cy1 = ((int)fminf(ey + RADp, 255.0f)) >> 3;
    for (int cy = cy0; cy <= cy1; cy++) {
        int s = __ldg(&cs[(cy << 5) + cx0]);
        int e = __ldg(&cs[(cy << 5) + cx1 + 1]);
        for (int k = s; k < e; k++) {
            float4 q = __ldg(&gp[k]);
            int idx  = __float_as_int(q.z);
            float dx = ex - q.x, dy = ey - q.y;
            float d = fmaf(dy, dy, dx * dx);
            if (d < bd || (d == bd && idx < bi)) { bd = d; bi = idx; }
        }
    }
}

// ---------------------------------------------------------------------------
// K3: decode ONE pixel per thread (512 blocks: latency-bound on libm chains +
// scattered grid loads + atomics, so resident-warp TLP beats per-thread ILP).
// First toucher of a bucket (atomicAdd returns 0) also writes lines_adj[g];
// the value depends only on g, so winner identity is irrelevant.
// Also resets the replay-scoped candidate counters.
// ---------------------------------------------------------------------------
__global__ void __launch_bounds__(256) k_match(const float* __restrict__ raw,
                                               float4* __restrict__ lines,
                                               float* __restrict__ counts,
                                               float* __restrict__ support) {
    int b = blockIdx.y;
    if (b == 0 && blockIdx.x == 0 && threadIdx.x == 0) {
        g_ccnt[0] = 0; g_ccnt[1] = 0;    // reset for next replay (topk consumed it)
    }
    const float* rb = raw + (size_t)b * 9 * HWp;
    const float4* gp = g_gpack[b];
    const int* cs = g_cellStart[b];
    int p = blockIdx.x * 256 + threadIdx.x;

    float r0 = rb[p];
    float r1 = rb[HWp + p];
    float r2 = rb[2 * HWp + p];
    float r3 = rb[3 * HWp + p];

    float md0 = sigf(r0), md1 = sigf(r1), md2 = sigf(r2);
    float d   = sigf(r3);
    float theta = (md0 - 0.5f) * 6.28318530717958647692f;
    float csn, ssn;
    sincosf(theta, &ssn, &csn);
    float yst = tanf(md1 * 1.57079632679489661923f);
    float yed = tanf(-md2 * 1.57079632679489661923f);
    float ds = d * SCALEp;
    float x0 = (float)(p & 255);
    float y0 = (float)(p >> 8);
    float l0 = fminf(fmaxf((csn - ssn * yst) * ds + x0, 0.0f), 255.0f);
    float l1 = fminf(fmaxf((ssn + csn * yst) * ds + y0, 0.0f), 255.0f);
    float l2 = fminf(fmaxf((csn - ssn * yed) * ds + x0, 0.0f), 255.0f);
    float l3 = fminf(fmaxf((ssn + csn * yed) * ds + y0, 0.0f), 255.0f);

    float bd1 = 1e30f, bd2 = 1e30f;
    int   bi1 = Jp,    bi2 = Jp;
    nearest(gp, cs, l0, l1, bd1, bi1);
    nearest(gp, cs, l2, l3, bd2, bi2);

    if (bd1 < J2Lp && bd2 < J2Lp && bi1 != bi2) {
        int imin = min(bi1, bi2), imax = max(bi1, bi2);
        int g = b * JJp + imin * Jp + imax;
        float old = atomicAdd(&counts[g], 1.0f);
        atomicAdd(&support[(size_t)g * 4 + 0], l0);
        atomicAdd(&support[(size_t)g * 4 + 1], l1);
        atomicAdd(&support[(size_t)g * 4 + 2], l2);
        atomicAdd(&support[(size_t)g * 4 + 3], l3);
        if (old == 0.0f) {
            float2 A  = g_juncs[b][imin];
            float2 Bq = g_juncs[b][imax];
            lines[g] = make_float4(A.x, A.y, Bq.x, Bq.y);
        }
    }
}

// ---------------------------------------------------------------------------
// Launch. Output layout: lines_adj [B*JJ*4] | counts [B*JJ] | support [B*JJ*4]
// ---------------------------------------------------------------------------
extern "C" void kernel_launch(void* const* d_in, const int* in_sizes, int n_in,
                              void* d_out, int out_size) {
    const float* raw = (const float*)d_in[0];
    float* out = (float*)d_out;
    float* counts  = out + (size_t)Bp * JJp * 4;
    float* support = counts + (size_t)Bp * JJp;

    dim3 gcand(TILES + ZBLKC, Bp);
    k_cand_zero<<<gcand, 1024>>>(raw, (float4*)out);  // zeroes 8.4 MB, fine chunks
    k_topk<<<Bp + ZBLKT, 1024>>>(raw, (float4*)out);  // zeroes 10.5 MB, fine chunks
    dim3 gmatch(HWp / 256, Bp);
    k_match<<<gmatch, 256>>>(raw, (float4*)out, counts, support);
}